// round 9
// baseline (speedup 1.0000x reference)
#include <cuda_runtime.h>
#include <cuda_fp16.h>
#include <cstddef>

#define Bv 4
#define Sv 1024
#define Dv 768
#define Hv 12
#define DHv 64
#define Mv 4096   // B*S
#define BHv 48    // B*H

// ---------------- scratch (device globals; no allocation allowed) ------------
__device__ float g_pre[Mv * Dv];                      // pre-LN buffer
__device__ __half g_hh[Mv * Dv];                      // hidden fp16
__device__ __half g_ctx[Mv * Dv];                     // ctx fp16
__device__ __half g_qh[Mv * Dv];                      // Q fp16 head layout
__device__ __half g_kh[Mv * Dv];                      // K fp16 head layout
__device__ __half g_vh[Mv * Dv];                      // V fp16 head layout
__device__ __half g_att[(size_t)BHv * Sv * Sv];       // e1 then probs2 (96 MB fp16)
__device__ __half g_wt[4 * Dv * Dv];                  // weights transposed fp16
__device__ __half g_vt[(size_t)BHv * DHv * Sv];       // V transposed per head, fp16
__device__ float g_psum[(size_t)BHv * Sv * 8];        // per-CTA row-sum partials
__device__ float g_inv1[(size_t)BHv * Sv];            // 1/sum1 per row

// ---------------- helpers ----------------------------------------------------
// fast exp on FMA pipe (rel err ~3e-6 for |x| < 80)
__device__ __forceinline__ float fexp(float x) {
    float t = x * 1.4426950408889634f;
    float r = t + 12582912.0f;
    int i = __float_as_int(r) - 0x4B400000;
    float f = t - (r - 12582912.0f);
    float g = f * 0.6931471805599453f;
    float e = 0.008333334f;
    e = fmaf(e, g, 0.041666667f);
    e = fmaf(e, g, 0.16666667f);
    e = fmaf(e, g, 0.5f);
    e = fmaf(e, g, 1.0f);
    e = fmaf(e, g, 1.0f);
    return __int_as_float(__float_as_int(e) + (i << 23));
}

__device__ __forceinline__ void mma_f16(float c[4], const unsigned a[4], const unsigned b[2]) {
    asm volatile(
        "mma.sync.aligned.m16n8k16.row.col.f32.f16.f16.f32 "
        "{%0,%1,%2,%3}, {%4,%5,%6,%7}, {%8,%9}, {%0,%1,%2,%3};\n"
        : "+f"(c[0]), "+f"(c[1]), "+f"(c[2]), "+f"(c[3])
        : "r"(a[0]), "r"(a[1]), "r"(a[2]), "r"(a[3]), "r"(b[0]), "r"(b[1]));
}

__device__ __forceinline__ float blockReduceN(float v, float* sh, int nwarp) {
    const int lane = threadIdx.x & 31;
    const int w = threadIdx.x >> 5;
#pragma unroll
    for (int o = 16; o > 0; o >>= 1) v += __shfl_xor_sync(0xffffffffu, v, o);
    if (lane == 0) sh[w] = v;
    __syncthreads();
    if (w == 0) {
        float x = (lane < nwarp) ? sh[lane] : 0.f;
#pragma unroll
        for (int o = 8; o > 0; o >>= 1) x += __shfl_xor_sync(0xffffffffu, x, o);
        if (lane == 0) sh[16] = x;
    }
    __syncthreads();
    return sh[16];
}

// ---------------- once-per-launch conversions ---------------------------------
__global__ __launch_bounds__(256) void hidden_to_h(
    const float* __restrict__ X, __half* __restrict__ Xh)
{
    int i = (blockIdx.x * 256 + threadIdx.x) * 8;
    float4 a = *reinterpret_cast<const float4*>(X + i);
    float4 b = *reinterpret_cast<const float4*>(X + i + 4);
    __half2 h0 = __floats2half2_rn(a.x, a.y);
    __half2 h1 = __floats2half2_rn(a.z, a.w);
    __half2 h2 = __floats2half2_rn(b.x, b.y);
    __half2 h3 = __floats2half2_rn(b.z, b.w);
    uint4 o;
    o.x = *reinterpret_cast<unsigned*>(&h0);
    o.y = *reinterpret_cast<unsigned*>(&h1);
    o.z = *reinterpret_cast<unsigned*>(&h2);
    o.w = *reinterpret_cast<unsigned*>(&h3);
    *reinterpret_cast<uint4*>(Xh + i) = o;
}

__global__ __launch_bounds__(256) void transpose_w4(
    const float* __restrict__ W0, const float* __restrict__ W1,
    const float* __restrict__ W2, const float* __restrict__ W3,
    __half* __restrict__ out)
{
    __shared__ float t[32][33];
    const float* W = (blockIdx.z == 0) ? W0 : (blockIdx.z == 1) ? W1
                   : (blockIdx.z == 2) ? W2 : W3;
    __half* O = out + (size_t)blockIdx.z * Dv * Dv;
    const int tx = threadIdx.x & 31, ty = threadIdx.x >> 5;
    const int k0 = blockIdx.x * 32, n0 = blockIdx.y * 32;
#pragma unroll
    for (int i = 0; i < 4; ++i)
        t[ty + 8 * i][tx] = W[(size_t)(k0 + ty + 8 * i) * Dv + n0 + tx];
    __syncthreads();
#pragma unroll
    for (int i = 0; i < 4; ++i)
        O[(size_t)(n0 + ty + 8 * i) * Dv + k0 + tx] = __float2half_rn(t[tx][ty + 8 * i]);
}

// V fp16 head layout [bh][s][dh] -> Vt fp16 [bh][dh][s]
__global__ __launch_bounds__(256) void transpose_v_h(
    const __half* __restrict__ V, __half* __restrict__ Vt)
{
    __shared__ __half t[32][34];
    const int bh = blockIdx.z;
    const int s0 = blockIdx.x * 32, d0 = blockIdx.y * 32;
    const __half* Vb = V + (size_t)bh * Sv * DHv;
    __half* Ob = Vt + (size_t)bh * DHv * Sv;
    const int tx = threadIdx.x & 31, ty = threadIdx.x >> 5;
#pragma unroll
    for (int i = 0; i < 4; ++i)
        t[ty + 8 * i][tx] = Vb[(size_t)(s0 + ty + 8 * i) * DHv + d0 + tx];
    __syncthreads();
#pragma unroll
    for (int i = 0; i < 4; ++i)
        Ob[(size_t)(d0 + ty + 8 * i) * Sv + s0 + tx] = t[tx][ty + 8 * i];
}

// ===== fp16 GEMM mainloop: A fp16 [M,K] row-major, Bt fp16 [N,K]; BK=32 ======
// accumulates into c[4][4][4] for a 128x128 CTA tile (64x32 warp tiles)
__device__ __forceinline__ void f16_gemm_main(
    const __half* __restrict__ A, const __half* __restrict__ Bt,
    int K, int m0, int n0, float c[4][4][4],
    __half (*As)[40], __half (*Bs)[40])
{
    const int tid = threadIdx.x, lane = tid & 31, warp = tid >> 5;
    const int wm = (warp >> 2) * 64, wn = (warp & 3) * 32;
    const int g = lane >> 2, qd = lane & 3;

    for (int k0 = 0; k0 < K; k0 += 32) {
#pragma unroll
        for (int it = 0; it < 2; ++it) {
            int idx = tid + it * 256;
            int row = idx >> 2, c8 = (idx & 3) * 8;
            *reinterpret_cast<uint4*>(&As[row][c8]) =
                *reinterpret_cast<const uint4*>(A + (size_t)(m0 + row) * K + k0 + c8);
            *reinterpret_cast<uint4*>(&Bs[row][c8]) =
                *reinterpret_cast<const uint4*>(Bt + (size_t)(n0 + row) * K + k0 + c8);
        }
        __syncthreads();
#pragma unroll
        for (int kk = 0; kk < 32; kk += 16) {
            unsigned af[4][4], bf[4][2];
#pragma unroll
            for (int mt = 0; mt < 4; ++mt) {
                int r = wm + mt * 16 + g;
                af[mt][0] = *reinterpret_cast<const unsigned*>(&As[r][kk + 2 * qd]);
                af[mt][1] = *reinterpret_cast<const unsigned*>(&As[r + 8][kk + 2 * qd]);
                af[mt][2] = *reinterpret_cast<const unsigned*>(&As[r][kk + 2 * qd + 8]);
                af[mt][3] = *reinterpret_cast<const unsigned*>(&As[r + 8][kk + 2 * qd + 8]);
            }
#pragma unroll
            for (int nt = 0; nt < 4; ++nt) {
                int cn = wn + nt * 8 + g;
                bf[nt][0] = *reinterpret_cast<const unsigned*>(&Bs[cn][kk + 2 * qd]);
                bf[nt][1] = *reinterpret_cast<const unsigned*>(&Bs[cn][kk + 2 * qd + 8]);
            }
#pragma unroll
            for (int mt = 0; mt < 4; ++mt)
#pragma unroll
                for (int nt = 0; nt < 4; ++nt) mma_f16(c[mt][nt], af[mt], bf[nt]);
        }
        __syncthreads();
    }
}

// ============ QKV projection: fp16 MMA, epilogue writes fp16 head layout =====
__global__ __launch_bounds__(256, 2) void gemm_qkv(
    const __half* __restrict__ A, const __half* __restrict__ Wt,
    const float* __restrict__ bq, const float* __restrict__ bk, const float* __restrict__ bvb,
    __half* __restrict__ qh, __half* __restrict__ kh, __half* __restrict__ vh)
{
    __shared__ __half As[128][40];
    __shared__ __half Bs[128][40];
    const __half* Bt = Wt + (size_t)blockIdx.z * Dv * Dv;
    const float* bias = (blockIdx.z == 0) ? bq : (blockIdx.z == 1) ? bk : bvb;
    __half* out = (blockIdx.z == 0) ? qh : (blockIdx.z == 1) ? kh : vh;
    const int m0 = blockIdx.y * 128, n0 = blockIdx.x * 128;
    const int lane = threadIdx.x & 31, warp = threadIdx.x >> 5;
    const int wm = (warp >> 2) * 64, wn = (warp & 3) * 32;
    const int g = lane >> 2, qd = lane & 3;

    float c[4][4][4];
#pragma unroll
    for (int mt = 0; mt < 4; ++mt)
#pragma unroll
        for (int nt = 0; nt < 4; ++nt)
#pragma unroll
            for (int i = 0; i < 4; ++i) c[mt][nt][i] = 0.f;

    f16_gemm_main(A, Bt, Dv, m0, n0, c, As, Bs);

#pragma unroll
    for (int mt = 0; mt < 4; ++mt) {
#pragma unroll
        for (int i = 0; i < 2; ++i) {
            int row = m0 + wm + mt * 16 + g + 8 * i;
            int b = row >> 10, s = row & 1023;
#pragma unroll
            for (int nt = 0; nt < 4; ++nt) {
                int col = n0 + wn + nt * 8 + 2 * qd;
                float2 bb = *reinterpret_cast<const float2*>(bias + col);
                int h = col >> 6, d = col & 63;
                *reinterpret_cast<__half2*>(out + ((size_t)(b * Hv + h) * Sv + s) * DHv + d) =
                    __floats2half2_rn(c[mt][nt][2 * i + 0] + bb.x,
                                      c[mt][nt][2 * i + 1] + bb.y);
            }
        }
    }
}

// ============ out-projection: fp16 MMA, +bias+resid(fp32) -> fp32 ============
__global__ __launch_bounds__(256, 2) void gemm_out(
    const __half* __restrict__ A, const __half* __restrict__ Bt,
    const float* __restrict__ bias, const float* __restrict__ resid,
    float* __restrict__ out)
{
    __shared__ __half As[128][40];
    __shared__ __half Bs[128][40];
    const int m0 = blockIdx.y * 128, n0 = blockIdx.x * 128;
    const int lane = threadIdx.x & 31, warp = threadIdx.x >> 5;
    const int wm = (warp >> 2) * 64, wn = (warp & 3) * 32;
    const int g = lane >> 2, qd = lane & 3;

    float c[4][4][4];
#pragma unroll
    for (int mt = 0; mt < 4; ++mt)
#pragma unroll
        for (int nt = 0; nt < 4; ++nt)
#pragma unroll
            for (int i = 0; i < 4; ++i) c[mt][nt][i] = 0.f;

    f16_gemm_main(A, Bt, Dv, m0, n0, c, As, Bs);

#pragma unroll
    for (int mt = 0; mt < 4; ++mt) {
#pragma unroll
        for (int i = 0; i < 2; ++i) {
            int row = m0 + wm + mt * 16 + g + 8 * i;
#pragma unroll
            for (int nt = 0; nt < 4; ++nt) {
                int col = n0 + wn + nt * 8 + 2 * qd;
                float2 bb = *reinterpret_cast<const float2*>(bias + col);
                float2 rv = *reinterpret_cast<const float2*>(resid + (size_t)row * Dv + col);
                float2 v;
                v.x = c[mt][nt][2 * i + 0] + bb.x + rv.x;
                v.y = c[mt][nt][2 * i + 1] + bb.y + rv.y;
                *reinterpret_cast<float2*>(out + (size_t)row * Dv + col) = v;
            }
        }
    }
}

// ====== qk fp16 MMA (whole-tile staging) + exp epilogue ======================
__global__ __launch_bounds__(256, 2) void qk_exp(
    const __half* __restrict__ Q, const __half* __restrict__ Km,
    const float* __restrict__ mask, __half* __restrict__ att,
    float* __restrict__ psum)
{
    __shared__ __half As[128][72];
    __shared__ __half Bs[128][72];
    __shared__ float sm_mask[128];
    __shared__ float sm_rs[128][4];
    const int tid = threadIdx.x, lane = tid & 31, warp = tid >> 5;
    const int wm = (warp >> 2) * 64, wn = (warp & 3) * 32;
    const int g = lane >> 2, qd = lane & 3;
    const int n0 = blockIdx.x * 128, m0 = blockIdx.y * 128;
    const int bh = blockIdx.z, bb = bh / Hv;
    const size_t base = (size_t)bh * Sv * DHv;

    if (tid < 128) sm_mask[tid] = mask[(size_t)bb * Sv + n0 + tid];

#pragma unroll
    for (int it = 0; it < 4; ++it) {
        int idx = tid + it * 256;
        int row = idx >> 3, c8 = (idx & 7) * 8;
        *reinterpret_cast<uint4*>(&As[row][c8]) =
            *reinterpret_cast<const uint4*>(Q + base + (size_t)(m0 + row) * DHv + c8);
        *reinterpret_cast<uint4*>(&Bs[row][c8]) =
            *reinterpret_cast<const uint4*>(Km + base + (size_t)(n0 + row) * DHv + c8);
    }
    __syncthreads();

    float c[4][4][4];
#pragma unroll
    for (int mt = 0; mt < 4; ++mt)
#pragma unroll
        for (int nt = 0; nt < 4; ++nt)
#pragma unroll
            for (int i = 0; i < 4; ++i) c[mt][nt][i] = 0.f;

#pragma unroll
    for (int kk = 0; kk < 64; kk += 16) {
        unsigned af[4][4], bf[4][2];
#pragma unroll
        for (int mt = 0; mt < 4; ++mt) {
            int r = wm + mt * 16 + g;
            af[mt][0] = *reinterpret_cast<const unsigned*>(&As[r][kk + 2 * qd]);
            af[mt][1] = *reinterpret_cast<const unsigned*>(&As[r + 8][kk + 2 * qd]);
            af[mt][2] = *reinterpret_cast<const unsigned*>(&As[r][kk + 2 * qd + 8]);
            af[mt][3] = *reinterpret_cast<const unsigned*>(&As[r + 8][kk + 2 * qd + 8]);
        }
#pragma unroll
        for (int nt = 0; nt < 4; ++nt) {
            int cn = wn + nt * 8 + g;
            bf[nt][0] = *reinterpret_cast<const unsigned*>(&Bs[cn][kk + 2 * qd]);
            bf[nt][1] = *reinterpret_cast<const unsigned*>(&Bs[cn][kk + 2 * qd + 8]);
        }
#pragma unroll
        for (int mt = 0; mt < 4; ++mt)
#pragma unroll
            for (int nt = 0; nt < 4; ++nt) mma_f16(c[mt][nt], af[mt], bf[nt]);
    }

    const size_t ab = (size_t)bh * Sv * Sv;
    float rsum[4][2];
#pragma unroll
    for (int mt = 0; mt < 4; ++mt) {
#pragma unroll
        for (int i = 0; i < 2; ++i) {
            rsum[mt][i] = 0.f;
            int row = m0 + wm + mt * 16 + g + 8 * i;
#pragma unroll
            for (int nt = 0; nt < 4; ++nt) {
                int lcol = wn + nt * 8 + 2 * qd;
                float e0 = fexp(fmaf(c[mt][nt][2 * i + 0], 0.125f, sm_mask[lcol]));
                float e1 = fexp(fmaf(c[mt][nt][2 * i + 1], 0.125f, sm_mask[lcol + 1]));
                rsum[mt][i] += e0 + e1;
                *reinterpret_cast<__half2*>(att + ab + (size_t)row * Sv + n0 + lcol) =
                    __floats2half2_rn(e0, e1);
            }
        }
    }
#pragma unroll
    for (int mt = 0; mt < 4; ++mt)
#pragma unroll
        for (int i = 0; i < 2; ++i) {
            float r = rsum[mt][i];
            r += __shfl_xor_sync(0xffffffffu, r, 1);
            r += __shfl_xor_sync(0xffffffffu, r, 2);
            if ((lane & 3) == 0) sm_rs[wm + mt * 16 + g + 8 * i][warp & 3] = r;
        }
    __syncthreads();
    if (tid < 128) {
        float s = (sm_rs[tid][0] + sm_rs[tid][1]) + (sm_rs[tid][2] + sm_rs[tid][3]);
        psum[((size_t)bh * Sv + m0 + tid) * 8 + blockIdx.x] = s;
    }
}

// ---------------- combine partials -> inv_sum1 --------------------------------
__global__ __launch_bounds__(256) void stats_combine(
    const float* __restrict__ psum, float* __restrict__ inv1)
{
    int i = blockIdx.x * 256 + threadIdx.x;
    const float* p = psum + (size_t)i * 8;
    float s = ((p[0] + p[1]) + (p[2] + p[3])) + ((p[4] + p[5]) + (p[6] + p[7]));
    inv1[i] = 1.f / s;
}

// ---- mix (round-6 structure, 512 threads, 2 cols/thread) --------------------
__global__ __launch_bounds__(512) void mix2(
    __half* __restrict__ att, const float* __restrict__ prev,
    const float* __restrict__ inv1g, const float* __restrict__ cw_g,
    const float* __restrict__ cb_g)
{
    __shared__ float cw[144];
    __shared__ float cb[12];
    __shared__ float red[17];
    const int t = threadIdx.x;
    const int qi = blockIdx.x;
    const int b = blockIdx.y;
    if (t < 144) cw[t] = cw_g[t];
    if (t < 12) cb[t] = cb_g[t];
    __syncthreads();

    float pv[12][2];
#pragma unroll
    for (int i = 0; i < 12; ++i) {
        __half2 h = *reinterpret_cast<const __half2*>(
            att + ((size_t)(b * Hv + i) * Sv + qi) * Sv + 2 * t);
        float inv = inv1g[(size_t)(b * Hv + i) * Sv + qi];
        pv[i][0] = __low2float(h) * inv;
        pv[i][1] = __high2float(h) * inv;
    }
    float pr[12][2];
#pragma unroll
    for (int i = 0; i < 12; ++i) {
        float2 p2 = *reinterpret_cast<const float2*>(
            prev + ((size_t)(b * Hv + i) * Sv + qi) * Sv + 2 * t);
        pr[i][0] = p2.x; pr[i][1] = p2.y;
    }

#pragma unroll
    for (int o = 0; o < 12; ++o) {
        float a0 = cb[o], a1 = cb[o];
#pragma unroll
        for (int i = 0; i < 12; ++i) {
            float w = cw[o * 12 + i];
            a0 = fmaf(w, pr[i][0], a0);
            a1 = fmaf(w, pr[i][1], a1);
        }
        float e0 = fexp(fmaf(0.5f, a0, 0.5f * pv[o][0]));
        float e1 = fexp(fmaf(0.5f, a1, 0.5f * pv[o][1]));
        float sum2 = blockReduceN(e0 + e1, red, 16);
        float inv2 = 1.f / sum2;
        *reinterpret_cast<__half2*>(
            att + ((size_t)(b * Hv + o) * Sv + qi) * Sv + 2 * t) =
            __floats2half2_rn(e0 * inv2, e1 * inv2);
    }
}

// ============ ctx = probs @ V, fp16 MMA, 128x64 tile; ctx stored fp16 ========
__global__ __launch_bounds__(256, 2) void av_f16(
    const __half* __restrict__ P, const __half* __restrict__ Vt, __half* __restrict__ ctx)
{
    __shared__ __half As[128][40];
    __shared__ __half Bs[64][40];
    const int tid = threadIdx.x, lane = tid & 31, warp = tid >> 5;
    const int wm = (warp >> 2) * 64, wn = (warp & 3) * 16;
    const int g = lane >> 2, qd = lane & 3;
    const int q0 = blockIdx.x * 128;
    const int bh = blockIdx.y;
    const int b = bh / Hv, h = bh % Hv;
    const __half* A = P + (size_t)bh * Sv * Sv;
    const __half* Vb = Vt + (size_t)bh * DHv * Sv;

    float c[4][2][4];
#pragma unroll
    for (int mt = 0; mt < 4; ++mt)
#pragma unroll
        for (int nt = 0; nt < 2; ++nt)
#pragma unroll
            for (int i = 0; i < 4; ++i) c[mt][nt][i] = 0.f;

    for (int k0 = 0; k0 < Sv; k0 += 32) {
#pragma unroll
        for (int it = 0; it < 2; ++it) {
            int idx = tid + it * 256;
            int row = idx >> 2, c8 = (idx & 3) * 8;
            uint4 v = *reinterpret_cast<const uint4*>(A + (size_t)(q0 + row) * Sv + k0 + c8);
            *reinterpret_cast<uint4*>(&As[row][c8]) = v;
        }
        {
            int row = tid >> 2, c8 = (tid & 3) * 8;
            uint4 v = *reinterpret_cast<const uint4*>(Vb + (size_t)row * Sv + k0 + c8);
            *reinterpret_cast<uint4*>(&Bs[row][c8]) = v;
        }
        __syncthreads();
#pragma unroll
        for (int kk = 0; kk < 32; kk += 16) {
            unsigned af[4][4], bf[2][2];
#pragma unroll
            for (int mt = 0; mt < 4; ++mt) {
                int r = wm + mt * 16 + g;
                af[mt][0] = *reinterpret_cast<const unsigned*>(&As[r][kk + 2 * qd]);
                af[mt][1] = *reinterpret_cast<const unsigned*>(&As[r + 8][kk + 2 * qd]);
                af[mt][2] = *reinterpret_cast<const unsigned*>(&As[r][kk + 2 * qd + 8]);
                af[mt][3] = *reinterpret_cast<const unsigned*>(&As[r + 8][kk + 2 * qd + 8]);
            }
#pragma unroll
            for (int nt = 0; nt < 2; ++nt) {
                int cn = wn + nt * 8 + g;
                bf[nt][0] = *reinterpret_cast<const unsigned*>(&Bs[cn][kk + 2 * qd]);
                bf[nt][1] = *reinterpret_cast<const unsigned*>(&Bs[cn][kk + 2 * qd + 8]);
            }
#pragma unroll
            for (int mt = 0; mt < 4; ++mt)
#pragma unroll
                for (int nt = 0; nt < 2; ++nt) mma_f16(c[mt][nt], af[mt], bf[nt]);
        }
        __syncthreads();
    }

#pragma unroll
    for (int mt = 0; mt < 4; ++mt) {
#pragma unroll
        for (int i = 0; i < 2; ++i) {
            int row = q0 + wm + mt * 16 + g + 8 * i;
#pragma unroll
            for (int nt = 0; nt < 2; ++nt) {
                int col = wn + nt * 8 + 2 * qd;
                *reinterpret_cast<__half2*>(ctx + ((size_t)b * Sv + row) * Dv + h * DHv + col) =
                    __floats2half2_rn(c[mt][nt][2 * i + 0], c[mt][nt][2 * i + 1]);
            }
        }
    }
}

// ---------------- LayerNorm over last dim (768) -------------------------------
__global__ __launch_bounds__(256) void layernorm_row(
    const float* __restrict__ pre, const float* __restrict__ w,
    const float* __restrict__ bb, float* __restrict__ out)
{
    __shared__ float red[17];
    const int t = threadIdx.x;
    const size_t row = blockIdx.x;
    const float* x = pre + row * Dv;

    float v[3];
#pragma unroll
    for (int j = 0; j < 3; ++j) v[j] = x[t + 256 * j];
    float s = v[0] + v[1] + v[2];
    s = blockReduceN(s, red, 8);
    float u = s * (1.f / 768.f);
    float d0 = v[0] - u, d1 = v[1] - u, d2 = v[2] - u;
    float sq = d0 * d0 + d1 * d1 + d2 * d2;
    sq = blockReduceN(sq, red, 8);
    float var = sq * (1.f / 768.f);
    float rr = rsqrtf(var + 1e-12f);
    float dd[3] = {d0, d1, d2};
#pragma unroll
    for (int j = 0; j < 3; ++j) {
        int ci = t + 256 * j;
        out[row * Dv + ci] = dd[j] * rr * w[ci] + bb[ci];
    }
}

// ------------------------------------------------------------------------------
extern "C" void kernel_launch(void* const* d_in, const int* in_sizes, int n_in,
                              void* d_out, int out_size)
{
    const float* hidden = (const float*)d_in[0];
    const float* mask   = (const float*)d_in[1];
    const float* prev   = (const float*)d_in[2];
    const float* Wq = (const float*)d_in[3];
    const float* bq = (const float*)d_in[4];
    const float* Wk = (const float*)d_in[5];
    const float* bk = (const float*)d_in[6];
    const float* Wv = (const float*)d_in[7];
    const float* bvp = (const float*)d_in[8];
    const float* cw = (const float*)d_in[9];
    const float* cb = (const float*)d_in[10];
    const float* Wo = (const float*)d_in[11];
    const float* bo = (const float*)d_in[12];
    const float* lnw = (const float*)d_in[13];
    const float* lnb = (const float*)d_in[14];
    float* out = (float*)d_out;

    float *pre, *psum, *inv1;
    __half *att, *wt, *vt, *qh, *kh, *vh, *hh, *ctx;
    cudaGetSymbolAddress((void**)&pre,  g_pre);
    cudaGetSymbolAddress((void**)&ctx,  g_ctx);
    cudaGetSymbolAddress((void**)&att,  g_att);
    cudaGetSymbolAddress((void**)&wt,   g_wt);
    cudaGetSymbolAddress((void**)&vt,   g_vt);
    cudaGetSymbolAddress((void**)&qh,   g_qh);
    cudaGetSymbolAddress((void**)&kh,   g_kh);
    cudaGetSymbolAddress((void**)&vh,   g_vh);
    cudaGetSymbolAddress((void**)&hh,   g_hh);
    cudaGetSymbolAddress((void**)&psum, g_psum);
    cudaGetSymbolAddress((void**)&inv1, g_inv1);

    hidden_to_h<<<(Mv * Dv) / (256 * 8), 256>>>(hidden, hh);
    transpose_w4<<<dim3(24, 24, 4), 256>>>(Wq, Wk, Wv, Wo, wt);

    gemm_qkv<<<dim3(Dv / 128, Mv / 128, 3), 256>>>(hh, wt, bq, bk, bvp, qh, kh, vh);

    transpose_v_h<<<dim3(Sv / 32, DHv / 32, BHv), 256>>>(vh, vt);

    qk_exp<<<dim3(Sv / 128, Sv / 128, BHv), 256>>>(qh, kh, mask, att, psum);

    stats_combine<<<(BHv * Sv) / 256, 256>>>(psum, inv1);

    mix2<<<dim3(Sv, Bv), 512>>>(att, prev, inv1, cw, cb);

    av_f16<<<dim3(Sv / 128, BHv), 256>>>(att, vt, ctx);

    gemm_out<<<dim3(Dv / 128, Mv / 128), 256>>>(ctx, wt + 3 * Dv * Dv, bo, hidden, pre);

    layernorm_row<<<Mv, 256>>>(pre, lnw, lnb, out);
}

// round 10
// speedup vs baseline: 1.7002x; 1.7002x over previous
#include <cuda_runtime.h>
#include <cuda_fp16.h>
#include <cstddef>

#define Bv 4
#define Sv 1024
#define Dv 768
#define Hv 12
#define DHv 64
#define Mv 4096   // B*S
#define BHv 48    // B*H

// ---------------- scratch (device globals; no allocation allowed) ------------
__device__ float g_pre[Mv * Dv];                      // pre-LN buffer
__device__ float g_ctx[Mv * Dv];                      // ctx fp32
__device__ __half g_hh[Mv * Dv];                      // hidden fp16
__device__ __half g_qh[Mv * Dv];                      // Q fp16 head layout
__device__ __half g_kh[Mv * Dv];                      // K fp16 head layout
__device__ __half g_vh[Mv * Dv];                      // V fp16 head layout
__device__ __half g_att[(size_t)BHv * Sv * Sv];       // e1 then probs2 (96 MB fp16)
__device__ __half g_wth[3 * Dv * Dv];                 // Wq,Wk,Wv transposed fp16
__device__ unsigned g_wt[Dv * Dv];                    // Wo transposed tf32
__device__ __half g_vt[(size_t)BHv * DHv * Sv];       // V transposed per head, fp16
__device__ float g_psum[(size_t)BHv * Sv * 8];        // per-CTA row-sum partials
__device__ float g_inv1[(size_t)BHv * Sv];            // 1/sum1 per row

// ---------------- helpers ----------------------------------------------------
__device__ __forceinline__ unsigned f2tf32(float x) {
    unsigned u;
    asm("cvt.rna.tf32.f32 %0, %1;" : "=r"(u) : "f"(x));
    return u;
}

// fast exp on FMA pipe (rel err ~3e-6 for |x| < 80)
__device__ __forceinline__ float fexp(float x) {
    float t = x * 1.4426950408889634f;
    float r = t + 12582912.0f;
    int i = __float_as_int(r) - 0x4B400000;
    float f = t - (r - 12582912.0f);
    float g = f * 0.6931471805599453f;
    float e = 0.008333334f;
    e = fmaf(e, g, 0.041666667f);
    e = fmaf(e, g, 0.16666667f);
    e = fmaf(e, g, 0.5f);
    e = fmaf(e, g, 1.0f);
    e = fmaf(e, g, 1.0f);
    return __int_as_float(__float_as_int(e) + (i << 23));
}

__device__ __forceinline__ void mma_tf32(float c[4], const unsigned a[4], const unsigned b[2]) {
    asm volatile(
        "mma.sync.aligned.m16n8k8.row.col.f32.tf32.tf32.f32 "
        "{%0,%1,%2,%3}, {%4,%5,%6,%7}, {%8,%9}, {%0,%1,%2,%3};\n"
        : "+f"(c[0]), "+f"(c[1]), "+f"(c[2]), "+f"(c[3])
        : "r"(a[0]), "r"(a[1]), "r"(a[2]), "r"(a[3]), "r"(b[0]), "r"(b[1]));
}

__device__ __forceinline__ void mma_f16(float c[4], const unsigned a[4], const unsigned b[2]) {
    asm volatile(
        "mma.sync.aligned.m16n8k16.row.col.f32.f16.f16.f32 "
        "{%0,%1,%2,%3}, {%4,%5,%6,%7}, {%8,%9}, {%0,%1,%2,%3};\n"
        : "+f"(c[0]), "+f"(c[1]), "+f"(c[2]), "+f"(c[3])
        : "r"(a[0]), "r"(a[1]), "r"(a[2]), "r"(a[3]), "r"(b[0]), "r"(b[1]));
}

__device__ __forceinline__ float blockReduce256(float v, float* sh) {
    const int lane = threadIdx.x & 31;
    const int w = threadIdx.x >> 5;
#pragma unroll
    for (int o = 16; o > 0; o >>= 1) v += __shfl_xor_sync(0xffffffffu, v, o);
    if (lane == 0) sh[w] = v;
    __syncthreads();
    if (w == 0) {
        float x = (lane < 8) ? sh[lane] : 0.f;
#pragma unroll
        for (int o = 4; o > 0; o >>= 1) x += __shfl_xor_sync(0xffffffffu, x, o);
        if (lane == 0) sh[8] = x;
    }
    __syncthreads();
    return sh[8];
}

// ---------------- once-per-launch conversions ---------------------------------
__global__ __launch_bounds__(256) void hidden_to_h(
    const float* __restrict__ X, __half* __restrict__ Xh)
{
    int i = (blockIdx.x * 256 + threadIdx.x) * 8;
    float4 a = *reinterpret_cast<const float4*>(X + i);
    float4 b = *reinterpret_cast<const float4*>(X + i + 4);
    __half2 h0 = __floats2half2_rn(a.x, a.y);
    __half2 h1 = __floats2half2_rn(a.z, a.w);
    __half2 h2 = __floats2half2_rn(b.x, b.y);
    __half2 h3 = __floats2half2_rn(b.z, b.w);
    uint4 o;
    o.x = *reinterpret_cast<unsigned*>(&h0);
    o.y = *reinterpret_cast<unsigned*>(&h1);
    o.z = *reinterpret_cast<unsigned*>(&h2);
    o.w = *reinterpret_cast<unsigned*>(&h3);
    *reinterpret_cast<uint4*>(Xh + i) = o;
}

// z<3: write fp16 (QKV); z==3: write tf32 bits (Wo)
__global__ __launch_bounds__(256) void transpose_w4(
    const float* __restrict__ W0, const float* __restrict__ W1,
    const float* __restrict__ W2, const float* __restrict__ W3,
    __half* __restrict__ outh, unsigned* __restrict__ outu)
{
    __shared__ float t[32][33];
    const float* W = (blockIdx.z == 0) ? W0 : (blockIdx.z == 1) ? W1
                   : (blockIdx.z == 2) ? W2 : W3;
    const int tx = threadIdx.x & 31, ty = threadIdx.x >> 5;
    const int k0 = blockIdx.x * 32, n0 = blockIdx.y * 32;
#pragma unroll
    for (int i = 0; i < 4; ++i)
        t[ty + 8 * i][tx] = W[(size_t)(k0 + ty + 8 * i) * Dv + n0 + tx];
    __syncthreads();
    if (blockIdx.z < 3) {
        __half* O = outh + (size_t)blockIdx.z * Dv * Dv;
#pragma unroll
        for (int i = 0; i < 4; ++i)
            O[(size_t)(n0 + ty + 8 * i) * Dv + k0 + tx] = __float2half_rn(t[tx][ty + 8 * i]);
    } else {
#pragma unroll
        for (int i = 0; i < 4; ++i)
            outu[(size_t)(n0 + ty + 8 * i) * Dv + k0 + tx] = f2tf32(t[tx][ty + 8 * i]);
    }
}

// V fp16 head layout [bh][s][dh] -> Vt fp16 [bh][dh][s]
__global__ __launch_bounds__(256) void transpose_v_h(
    const __half* __restrict__ V, __half* __restrict__ Vt)
{
    __shared__ __half t[32][34];
    const int bh = blockIdx.z;
    const int s0 = blockIdx.x * 32, d0 = blockIdx.y * 32;
    const __half* Vb = V + (size_t)bh * Sv * DHv;
    __half* Ob = Vt + (size_t)bh * DHv * Sv;
    const int tx = threadIdx.x & 31, ty = threadIdx.x >> 5;
#pragma unroll
    for (int i = 0; i < 4; ++i)
        t[ty + 8 * i][tx] = Vb[(size_t)(s0 + ty + 8 * i) * DHv + d0 + tx];
    __syncthreads();
#pragma unroll
    for (int i = 0; i < 4; ++i)
        Ob[(size_t)(d0 + ty + 8 * i) * Sv + s0 + tx] = t[tx][ty + 8 * i];
}

// ============ QKV projection: fp16 MMA (BK=32), epilogue fp16 head layout ====
__global__ __launch_bounds__(256, 2) void gemm_qkv(
    const __half* __restrict__ A, const __half* __restrict__ Wt,
    const float* __restrict__ bq, const float* __restrict__ bk, const float* __restrict__ bvb,
    __half* __restrict__ qh, __half* __restrict__ kh, __half* __restrict__ vh)
{
    __shared__ __half As[128][40];
    __shared__ __half Bs[128][40];
    const __half* Bt = Wt + (size_t)blockIdx.z * Dv * Dv;
    const float* bias = (blockIdx.z == 0) ? bq : (blockIdx.z == 1) ? bk : bvb;
    __half* out = (blockIdx.z == 0) ? qh : (blockIdx.z == 1) ? kh : vh;
    const int m0 = blockIdx.y * 128, n0 = blockIdx.x * 128;
    const int tid = threadIdx.x, lane = tid & 31, warp = tid >> 5;
    const int wm = (warp >> 2) * 64, wn = (warp & 3) * 32;
    const int g = lane >> 2, qd = lane & 3;

    float c[4][4][4];
#pragma unroll
    for (int mt = 0; mt < 4; ++mt)
#pragma unroll
        for (int nt = 0; nt < 4; ++nt)
#pragma unroll
            for (int i = 0; i < 4; ++i) c[mt][nt][i] = 0.f;

    for (int k0 = 0; k0 < Dv; k0 += 32) {
#pragma unroll
        for (int it = 0; it < 2; ++it) {
            int idx = tid + it * 256;
            int row = idx >> 2, c8 = (idx & 3) * 8;
            *reinterpret_cast<uint4*>(&As[row][c8]) =
                *reinterpret_cast<const uint4*>(A + (size_t)(m0 + row) * Dv + k0 + c8);
            *reinterpret_cast<uint4*>(&Bs[row][c8]) =
                *reinterpret_cast<const uint4*>(Bt + (size_t)(n0 + row) * Dv + k0 + c8);
        }
        __syncthreads();
#pragma unroll
        for (int kk = 0; kk < 32; kk += 16) {
            unsigned af[4][4], bf[4][2];
#pragma unroll
            for (int mt = 0; mt < 4; ++mt) {
                int r = wm + mt * 16 + g;
                af[mt][0] = *reinterpret_cast<const unsigned*>(&As[r][kk + 2 * qd]);
                af[mt][1] = *reinterpret_cast<const unsigned*>(&As[r + 8][kk + 2 * qd]);
                af[mt][2] = *reinterpret_cast<const unsigned*>(&As[r][kk + 2 * qd + 8]);
                af[mt][3] = *reinterpret_cast<const unsigned*>(&As[r + 8][kk + 2 * qd + 8]);
            }
#pragma unroll
            for (int nt = 0; nt < 4; ++nt) {
                int cn = wn + nt * 8 + g;
                bf[nt][0] = *reinterpret_cast<const unsigned*>(&Bs[cn][kk + 2 * qd]);
                bf[nt][1] = *reinterpret_cast<const unsigned*>(&Bs[cn][kk + 2 * qd + 8]);
            }
#pragma unroll
            for (int mt = 0; mt < 4; ++mt)
#pragma unroll
                for (int nt = 0; nt < 4; ++nt) mma_f16(c[mt][nt], af[mt], bf[nt]);
        }
        __syncthreads();
    }

#pragma unroll
    for (int mt = 0; mt < 4; ++mt) {
#pragma unroll
        for (int i = 0; i < 2; ++i) {
            int row = m0 + wm + mt * 16 + g + 8 * i;
            int b = row >> 10, s = row & 1023;
#pragma unroll
            for (int nt = 0; nt < 4; ++nt) {
                int col = n0 + wn + nt * 8 + 2 * qd;
                float2 bb = *reinterpret_cast<const float2*>(bias + col);
                int h = col >> 6, d = col & 63;
                *reinterpret_cast<__half2*>(out + ((size_t)(b * Hv + h) * Sv + s) * DHv + d) =
                    __floats2half2_rn(c[mt][nt][2 * i + 0] + bb.x,
                                      c[mt][nt][2 * i + 1] + bb.y);
            }
        }
    }
}

// ============ out-projection: tf32 MMA, fp32 A, +bias+resid (round-8) ========
__global__ __launch_bounds__(256, 2) void gemm_out(
    const float* __restrict__ A, const unsigned* __restrict__ Bt,
    const float* __restrict__ bias, const float* __restrict__ resid,
    float* __restrict__ out)
{
    const int m0 = blockIdx.y * 128, n0 = blockIdx.x * 128;
    __shared__ unsigned As[128][20];
    __shared__ unsigned Bs[128][20];
    const int tid = threadIdx.x, lane = tid & 31, warp = tid >> 5;
    const int wm = (warp >> 2) * 64, wn = (warp & 3) * 32;
    const int g = lane >> 2, q = lane & 3;

    float c[4][4][4];
#pragma unroll
    for (int mt = 0; mt < 4; ++mt)
#pragma unroll
        for (int nt = 0; nt < 4; ++nt)
#pragma unroll
            for (int i = 0; i < 4; ++i) c[mt][nt][i] = 0.f;

    for (int k0 = 0; k0 < Dv; k0 += 16) {
#pragma unroll
        for (int it = 0; it < 2; ++it) {
            int idx = tid + it * 256;
            int row = idx >> 2, col = (idx & 3) * 4;
            float4 a = *reinterpret_cast<const float4*>(A + (size_t)(m0 + row) * Dv + k0 + col);
            uint4 av;
            av.x = f2tf32(a.x); av.y = f2tf32(a.y); av.z = f2tf32(a.z); av.w = f2tf32(a.w);
            *reinterpret_cast<uint4*>(&As[row][col]) = av;
            uint4 bvv = *reinterpret_cast<const uint4*>(Bt + (size_t)(n0 + row) * Dv + k0 + col);
            *reinterpret_cast<uint4*>(&Bs[row][col]) = bvv;
        }
        __syncthreads();
#pragma unroll
        for (int kk = 0; kk < 16; kk += 8) {
            unsigned af[4][4], bf[4][2];
#pragma unroll
            for (int mt = 0; mt < 4; ++mt) {
                int r = wm + mt * 16 + g;
                af[mt][0] = As[r][kk + q];
                af[mt][1] = As[r + 8][kk + q];
                af[mt][2] = As[r][kk + q + 4];
                af[mt][3] = As[r + 8][kk + q + 4];
            }
#pragma unroll
            for (int nt = 0; nt < 4; ++nt) {
                int cn = wn + nt * 8 + g;
                bf[nt][0] = Bs[cn][kk + q];
                bf[nt][1] = Bs[cn][kk + q + 4];
            }
#pragma unroll
            for (int mt = 0; mt < 4; ++mt)
#pragma unroll
                for (int nt = 0; nt < 4; ++nt) mma_tf32(c[mt][nt], af[mt], bf[nt]);
        }
        __syncthreads();
    }

#pragma unroll
    for (int mt = 0; mt < 4; ++mt) {
#pragma unroll
        for (int i = 0; i < 2; ++i) {
            int row = m0 + wm + mt * 16 + g + 8 * i;
#pragma unroll
            for (int nt = 0; nt < 4; ++nt) {
                int col = n0 + wn + nt * 8 + 2 * q;
                float2 bb = *reinterpret_cast<const float2*>(bias + col);
                float2 rv = *reinterpret_cast<const float2*>(resid + (size_t)row * Dv + col);
                float2 v;
                v.x = c[mt][nt][2 * i + 0] + bb.x + rv.x;
                v.y = c[mt][nt][2 * i + 1] + bb.y + rv.y;
                *reinterpret_cast<float2*>(out + (size_t)row * Dv + col) = v;
            }
        }
    }
}

// ====== qk fp16 MMA (whole-tile staging) + exp epilogue ======================
__global__ __launch_bounds__(256, 2) void qk_exp(
    const __half* __restrict__ Q, const __half* __restrict__ Km,
    const float* __restrict__ mask, __half* __restrict__ att,
    float* __restrict__ psum)
{
    __shared__ __half As[128][72];
    __shared__ __half Bs[128][72];
    __shared__ float sm_mask[128];
    __shared__ float sm_rs[128][4];
    const int tid = threadIdx.x, lane = tid & 31, warp = tid >> 5;
    const int wm = (warp >> 2) * 64, wn = (warp & 3) * 32;
    const int g = lane >> 2, qd = lane & 3;
    const int n0 = blockIdx.x * 128, m0 = blockIdx.y * 128;
    const int bh = blockIdx.z, bb = bh / Hv;
    const size_t base = (size_t)bh * Sv * DHv;

    if (tid < 128) sm_mask[tid] = mask[(size_t)bb * Sv + n0 + tid];

#pragma unroll
    for (int it = 0; it < 4; ++it) {
        int idx = tid + it * 256;
        int row = idx >> 3, c8 = (idx & 7) * 8;
        *reinterpret_cast<uint4*>(&As[row][c8]) =
            *reinterpret_cast<const uint4*>(Q + base + (size_t)(m0 + row) * DHv + c8);
        *reinterpret_cast<uint4*>(&Bs[row][c8]) =
            *reinterpret_cast<const uint4*>(Km + base + (size_t)(n0 + row) * DHv + c8);
    }
    __syncthreads();

    float c[4][4][4];
#pragma unroll
    for (int mt = 0; mt < 4; ++mt)
#pragma unroll
        for (int nt = 0; nt < 4; ++nt)
#pragma unroll
            for (int i = 0; i < 4; ++i) c[mt][nt][i] = 0.f;

#pragma unroll
    for (int kk = 0; kk < 64; kk += 16) {
        unsigned af[4][4], bf[4][2];
#pragma unroll
        for (int mt = 0; mt < 4; ++mt) {
            int r = wm + mt * 16 + g;
            af[mt][0] = *reinterpret_cast<const unsigned*>(&As[r][kk + 2 * qd]);
            af[mt][1] = *reinterpret_cast<const unsigned*>(&As[r + 8][kk + 2 * qd]);
            af[mt][2] = *reinterpret_cast<const unsigned*>(&As[r][kk + 2 * qd + 8]);
            af[mt][3] = *reinterpret_cast<const unsigned*>(&As[r + 8][kk + 2 * qd + 8]);
        }
#pragma unroll
        for (int nt = 0; nt < 4; ++nt) {
            int cn = wn + nt * 8 + g;
            bf[nt][0] = *reinterpret_cast<const unsigned*>(&Bs[cn][kk + 2 * qd]);
            bf[nt][1] = *reinterpret_cast<const unsigned*>(&Bs[cn][kk + 2 * qd + 8]);
        }
#pragma unroll
        for (int mt = 0; mt < 4; ++mt)
#pragma unroll
            for (int nt = 0; nt < 4; ++nt) mma_f16(c[mt][nt], af[mt], bf[nt]);
    }

    const size_t ab = (size_t)bh * Sv * Sv;
    float rsum[4][2];
#pragma unroll
    for (int mt = 0; mt < 4; ++mt) {
#pragma unroll
        for (int i = 0; i < 2; ++i) {
            rsum[mt][i] = 0.f;
            int row = m0 + wm + mt * 16 + g + 8 * i;
#pragma unroll
            for (int nt = 0; nt < 4; ++nt) {
                int lcol = wn + nt * 8 + 2 * qd;
                float e0 = fexp(fmaf(c[mt][nt][2 * i + 0], 0.125f, sm_mask[lcol]));
                float e1 = fexp(fmaf(c[mt][nt][2 * i + 1], 0.125f, sm_mask[lcol + 1]));
                rsum[mt][i] += e0 + e1;
                *reinterpret_cast<__half2*>(att + ab + (size_t)row * Sv + n0 + lcol) =
                    __floats2half2_rn(e0, e1);
            }
        }
    }
#pragma unroll
    for (int mt = 0; mt < 4; ++mt)
#pragma unroll
        for (int i = 0; i < 2; ++i) {
            float r = rsum[mt][i];
            r += __shfl_xor_sync(0xffffffffu, r, 1);
            r += __shfl_xor_sync(0xffffffffu, r, 2);
            if ((lane & 3) == 0) sm_rs[wm + mt * 16 + g + 8 * i][warp & 3] = r;
        }
    __syncthreads();
    if (tid < 128) {
        float s = (sm_rs[tid][0] + sm_rs[tid][1]) + (sm_rs[tid][2] + sm_rs[tid][3]);
        psum[((size_t)bh * Sv + m0 + tid) * 8 + blockIdx.x] = s;
    }
}

// ---------------- combine partials -> inv_sum1 --------------------------------
__global__ __launch_bounds__(256) void stats_combine(
    const float* __restrict__ psum, float* __restrict__ inv1)
{
    int i = blockIdx.x * 256 + threadIdx.x;
    const float* p = psum + (size_t)i * 8;
    float s = ((p[0] + p[1]) + (p[2] + p[3])) + ((p[4] + p[5]) + (p[6] + p[7]));
    inv1[i] = 1.f / s;
}

// ---- mix (round-8 proven structure): pv/pr loaded once, per-head blockReduce
__global__ __launch_bounds__(256) void mix2(
    __half* __restrict__ att, const float* __restrict__ prev,
    const float* __restrict__ inv1g, const float* __restrict__ cw_g,
    const float* __restrict__ cb_g)
{
    __shared__ float cw[144];
    __shared__ float cb[12];
    __shared__ float red[9];
    const int t = threadIdx.x;
    const int qi = blockIdx.x;
    const int b = blockIdx.y;
    if (t < 144) cw[t] = cw_g[t];
    if (t < 12) cb[t] = cb_g[t];
    __syncthreads();

    float pv[12][4];
#pragma unroll
    for (int i = 0; i < 12; ++i) {
        const __half2* pa = reinterpret_cast<const __half2*>(
            att + ((size_t)(b * Hv + i) * Sv + qi) * Sv + 4 * t);
        __half2 h0 = pa[0], h1 = pa[1];
        float inv = inv1g[(size_t)(b * Hv + i) * Sv + qi];
        pv[i][0] = __low2float(h0) * inv;  pv[i][1] = __high2float(h0) * inv;
        pv[i][2] = __low2float(h1) * inv;  pv[i][3] = __high2float(h1) * inv;
    }
    float pr[12][4];
#pragma unroll
    for (int i = 0; i < 12; ++i) {
        float4 p4 = *reinterpret_cast<const float4*>(
            prev + ((size_t)(b * Hv + i) * Sv + qi) * Sv + 4 * t);
        pr[i][0] = p4.x; pr[i][1] = p4.y; pr[i][2] = p4.z; pr[i][3] = p4.w;
    }

#pragma unroll
    for (int o = 0; o < 12; ++o) {
        float e2[4], ls = 0.f;
#pragma unroll
        for (int j = 0; j < 4; ++j) {
            float a = cb[o];
#pragma unroll
            for (int i = 0; i < 12; ++i) a = fmaf(cw[o * 12 + i], pr[i][j], a);
            float mixd = fmaf(0.5f, a, 0.5f * pv[o][j]);
            e2[j] = fexp(mixd);
            ls += e2[j];
        }
        float sum2 = blockReduce256(ls, red);
        float inv2 = 1.f / sum2;
        __half2* oa = reinterpret_cast<__half2*>(
            att + ((size_t)(b * Hv + o) * Sv + qi) * Sv + 4 * t);
        oa[0] = __floats2half2_rn(e2[0] * inv2, e2[1] * inv2);
        oa[1] = __floats2half2_rn(e2[2] * inv2, e2[3] * inv2);
    }
}

// ============ ctx = probs @ V, fp16 MMA m16n8k16, 128x64 tile; ctx fp32 ======
__global__ __launch_bounds__(256, 2) void av_f16(
    const __half* __restrict__ P, const __half* __restrict__ Vt, float* __restrict__ ctx)
{
    __shared__ __half As[128][40];
    __shared__ __half Bs[64][40];
    const int tid = threadIdx.x, lane = tid & 31, warp = tid >> 5;
    const int wm = (warp >> 2) * 64, wn = (warp & 3) * 16;
    const int g = lane >> 2, qd = lane & 3;
    const int q0 = blockIdx.x * 128;
    const int bh = blockIdx.y;
    const int b = bh / Hv, h = bh % Hv;
    const __half* A = P + (size_t)bh * Sv * Sv;
    const __half* Vb = Vt + (size_t)bh * DHv * Sv;

    float c[4][2][4];
#pragma unroll
    for (int mt = 0; mt < 4; ++mt)
#pragma unroll
        for (int nt = 0; nt < 2; ++nt)
#pragma unroll
            for (int i = 0; i < 4; ++i) c[mt][nt][i] = 0.f;

    for (int k0 = 0; k0 < Sv; k0 += 32) {
#pragma unroll
        for (int it = 0; it < 2; ++it) {
            int idx = tid + it * 256;
            int row = idx >> 2, c8 = (idx & 3) * 8;
            uint4 v = *reinterpret_cast<const uint4*>(A + (size_t)(q0 + row) * Sv + k0 + c8);
            *reinterpret_cast<uint4*>(&As[row][c8]) = v;
        }
        {
            int row = tid >> 2, c8 = (tid & 3) * 8;
            uint4 v = *reinterpret_cast<const uint4*>(Vb + (size_t)row * Sv + k0 + c8);
            *reinterpret_cast<uint4*>(&Bs[row][c8]) = v;
        }
        __syncthreads();
#pragma unroll
        for (int kk = 0; kk < 32; kk += 16) {
            unsigned af[4][4], bf[2][2];
#pragma unroll
            for (int mt = 0; mt < 4; ++mt) {
                int r = wm + mt * 16 + g;
                af[mt][0] = *reinterpret_cast<const unsigned*>(&As[r][kk + 2 * qd]);
                af[mt][1] = *reinterpret_cast<const unsigned*>(&As[r + 8][kk + 2 * qd]);
                af[mt][2] = *reinterpret_cast<const unsigned*>(&As[r][kk + 2 * qd + 8]);
                af[mt][3] = *reinterpret_cast<const unsigned*>(&As[r + 8][kk + 2 * qd + 8]);
            }
#pragma unroll
            for (int nt = 0; nt < 2; ++nt) {
                int cn = wn + nt * 8 + g;
                bf[nt][0] = *reinterpret_cast<const unsigned*>(&Bs[cn][kk + 2 * qd]);
                bf[nt][1] = *reinterpret_cast<const unsigned*>(&Bs[cn][kk + 2 * qd + 8]);
            }
#pragma unroll
            for (int mt = 0; mt < 4; ++mt)
#pragma unroll
                for (int nt = 0; nt < 2; ++nt) mma_f16(c[mt][nt], af[mt], bf[nt]);
        }
        __syncthreads();
    }

#pragma unroll
    for (int mt = 0; mt < 4; ++mt) {
#pragma unroll
        for (int i = 0; i < 2; ++i) {
            int row = q0 + wm + mt * 16 + g + 8 * i;
#pragma unroll
            for (int nt = 0; nt < 2; ++nt) {
                int col = wn + nt * 8 + 2 * qd;
                float2 v;
                v.x = c[mt][nt][2 * i + 0];
                v.y = c[mt][nt][2 * i + 1];
                *reinterpret_cast<float2*>(ctx + ((size_t)b * Sv + row) * Dv + h * DHv + col) = v;
            }
        }
    }
}

// ---------------- LayerNorm over last dim (768) -------------------------------
__global__ __launch_bounds__(256) void layernorm_row(
    const float* __restrict__ pre, const float* __restrict__ w,
    const float* __restrict__ bb, float* __restrict__ out)
{
    __shared__ float red[9];
    const int t = threadIdx.x;
    const size_t row = blockIdx.x;
    const float* x = pre + row * Dv;

    float v[3];
#pragma unroll
    for (int j = 0; j < 3; ++j) v[j] = x[t + 256 * j];
    float s = v[0] + v[1] + v[2];
    s = blockReduce256(s, red);
    float u = s * (1.f / 768.f);
    float d0 = v[0] - u, d1 = v[1] - u, d2 = v[2] - u;
    float sq = d0 * d0 + d1 * d1 + d2 * d2;
    sq = blockReduce256(sq, red);
    float var = sq * (1.f / 768.f);
    float rr = rsqrtf(var + 1e-12f);
    float dd[3] = {d0, d1, d2};
#pragma unroll
    for (int j = 0; j < 3; ++j) {
        int ci = t + 256 * j;
        out[row * Dv + ci] = dd[j] * rr * w[ci] + bb[ci];
    }
}

// ------------------------------------------------------------------------------
extern "C" void kernel_launch(void* const* d_in, const int* in_sizes, int n_in,
                              void* d_out, int out_size)
{
    const float* hidden = (const float*)d_in[0];
    const float* mask   = (const float*)d_in[1];
    const float* prev   = (const float*)d_in[2];
    const float* Wq = (const float*)d_in[3];
    const float* bq = (const float*)d_in[4];
    const float* Wk = (const float*)d_in[5];
    const float* bk = (const float*)d_in[6];
    const float* Wv = (const float*)d_in[7];
    const float* bvp = (const float*)d_in[8];
    const float* cw = (const float*)d_in[9];
    const float* cb = (const float*)d_in[10];
    const float* Wo = (const float*)d_in[11];
    const float* bo = (const float*)d_in[12];
    const float* lnw = (const float*)d_in[13];
    const float* lnb = (const float*)d_in[14];
    float* out = (float*)d_out;

    float *pre, *ctx, *psum, *inv1;
    unsigned *wt;
    __half *att, *wth, *vt, *qh, *kh, *vh, *hh;
    cudaGetSymbolAddress((void**)&pre,  g_pre);
    cudaGetSymbolAddress((void**)&ctx,  g_ctx);
    cudaGetSymbolAddress((void**)&att,  g_att);
    cudaGetSymbolAddress((void**)&wt,   g_wt);
    cudaGetSymbolAddress((void**)&wth,  g_wth);
    cudaGetSymbolAddress((void**)&vt,   g_vt);
    cudaGetSymbolAddress((void**)&qh,   g_qh);
    cudaGetSymbolAddress((void**)&kh,   g_kh);
    cudaGetSymbolAddress((void**)&vh,   g_vh);
    cudaGetSymbolAddress((void**)&hh,   g_hh);
    cudaGetSymbolAddress((void**)&psum, g_psum);
    cudaGetSymbolAddress((void**)&inv1, g_inv1);

    hidden_to_h<<<(Mv * Dv) / (256 * 8), 256>>>(hidden, hh);
    transpose_w4<<<dim3(24, 24, 4), 256>>>(Wq, Wk, Wv, Wo, wth, wt);

    gemm_qkv<<<dim3(Dv / 128, Mv / 128, 3), 256>>>(hh, wth, bq, bk, bvp, qh, kh, vh);

    transpose_v_h<<<dim3(Sv / 32, DHv / 32, BHv), 256>>>(vh, vt);

    qk_exp<<<dim3(Sv / 128, Sv / 128, BHv), 256>>>(qh, kh, mask, att, psum);

    stats_combine<<<(BHv * Sv) / 256, 256>>>(psum, inv1);

    mix2<<<dim3(Sv, Bv), 256>>>(att, prev, inv1, cw, cb);

    av_f16<<<dim3(Sv / 128, BHv), 256>>>(att, vt, ctx);

    gemm_out<<<dim3(Dv / 128, Mv / 128), 256>>>(ctx, wt, bo, hidden, pre);

    layernorm_row<<<Mv, 256>>>(pre, lnw, lnb, out);
}

// round 11
// speedup vs baseline: 1.8617x; 1.0950x over previous
#include <cuda_runtime.h>
#include <cuda_fp16.h>
#include <cstddef>

#define Bv 4
#define Sv 1024
#define Dv 768
#define Hv 12
#define DHv 64
#define Mv 4096   // B*S
#define BHv 48    // B*H

// ---------------- scratch (device globals; no allocation allowed) ------------
__device__ float g_pre[Mv * Dv];                      // pre-LN buffer
__device__ __half g_ctx[Mv * Dv];                     // ctx fp16
__device__ __half g_hh[Mv * Dv];                      // hidden fp16
__device__ __half g_qh[Mv * Dv];                      // Q fp16 head layout
__device__ __half g_kh[Mv * Dv];                      // K fp16 head layout
__device__ __half g_vh[Mv * Dv];                      // V fp16 head layout
__device__ __half g_att[(size_t)BHv * Sv * Sv];       // e1 then probs2 (96 MB fp16)
__device__ __half g_wth[4 * Dv * Dv];                 // Wq,Wk,Wv,Wo transposed fp16
__device__ __half g_vt[(size_t)BHv * DHv * Sv];       // V transposed per head, fp16
__device__ float g_psum[(size_t)BHv * Sv * 8];        // per-CTA row-sum partials
__device__ float g_inv1[(size_t)BHv * Sv];            // 1/sum1 per row

// ---------------- helpers ----------------------------------------------------
// fast exp on FMA pipe (rel err ~3e-6 for |x| < 80)
__device__ __forceinline__ float fexp(float x) {
    float t = x * 1.4426950408889634f;
    float r = t + 12582912.0f;
    int i = __float_as_int(r) - 0x4B400000;
    float f = t - (r - 12582912.0f);
    float g = f * 0.6931471805599453f;
    float e = 0.008333334f;
    e = fmaf(e, g, 0.041666667f);
    e = fmaf(e, g, 0.16666667f);
    e = fmaf(e, g, 0.5f);
    e = fmaf(e, g, 1.0f);
    e = fmaf(e, g, 1.0f);
    return __int_as_float(__float_as_int(e) + (i << 23));
}

__device__ __forceinline__ void mma_f16(float c[4], const unsigned a[4], const unsigned b[2]) {
    asm volatile(
        "mma.sync.aligned.m16n8k16.row.col.f32.f16.f16.f32 "
        "{%0,%1,%2,%3}, {%4,%5,%6,%7}, {%8,%9}, {%0,%1,%2,%3};\n"
        : "+f"(c[0]), "+f"(c[1]), "+f"(c[2]), "+f"(c[3])
        : "r"(a[0]), "r"(a[1]), "r"(a[2]), "r"(a[3]), "r"(b[0]), "r"(b[1]));
}

__device__ __forceinline__ float blockReduce256(float v, float* sh) {
    const int lane = threadIdx.x & 31;
    const int w = threadIdx.x >> 5;
#pragma unroll
    for (int o = 16; o > 0; o >>= 1) v += __shfl_xor_sync(0xffffffffu, v, o);
    if (lane == 0) sh[w] = v;
    __syncthreads();
    if (w == 0) {
        float x = (lane < 8) ? sh[lane] : 0.f;
#pragma unroll
        for (int o = 4; o > 0; o >>= 1) x += __shfl_xor_sync(0xffffffffu, x, o);
        if (lane == 0) sh[8] = x;
    }
    __syncthreads();
    return sh[8];
}

// ---------------- once-per-launch conversions ---------------------------------
__global__ __launch_bounds__(256) void hidden_to_h(
    const float* __restrict__ X, __half* __restrict__ Xh)
{
    int i = (blockIdx.x * 256 + threadIdx.x) * 8;
    float4 a = *reinterpret_cast<const float4*>(X + i);
    float4 b = *reinterpret_cast<const float4*>(X + i + 4);
    __half2 h0 = __floats2half2_rn(a.x, a.y);
    __half2 h1 = __floats2half2_rn(a.z, a.w);
    __half2 h2 = __floats2half2_rn(b.x, b.y);
    __half2 h3 = __floats2half2_rn(b.z, b.w);
    uint4 o;
    o.x = *reinterpret_cast<unsigned*>(&h0);
    o.y = *reinterpret_cast<unsigned*>(&h1);
    o.z = *reinterpret_cast<unsigned*>(&h2);
    o.w = *reinterpret_cast<unsigned*>(&h3);
    *reinterpret_cast<uint4*>(Xh + i) = o;
}

// all 4 weights -> fp16 transposed [N][K]
__global__ __launch_bounds__(256) void transpose_w4(
    const float* __restrict__ W0, const float* __restrict__ W1,
    const float* __restrict__ W2, const float* __restrict__ W3,
    __half* __restrict__ outh)
{
    __shared__ float t[32][33];
    const float* W = (blockIdx.z == 0) ? W0 : (blockIdx.z == 1) ? W1
                   : (blockIdx.z == 2) ? W2 : W3;
    __half* O = outh + (size_t)blockIdx.z * Dv * Dv;
    const int tx = threadIdx.x & 31, ty = threadIdx.x >> 5;
    const int k0 = blockIdx.x * 32, n0 = blockIdx.y * 32;
#pragma unroll
    for (int i = 0; i < 4; ++i)
        t[ty + 8 * i][tx] = W[(size_t)(k0 + ty + 8 * i) * Dv + n0 + tx];
    __syncthreads();
#pragma unroll
    for (int i = 0; i < 4; ++i)
        O[(size_t)(n0 + ty + 8 * i) * Dv + k0 + tx] = __float2half_rn(t[tx][ty + 8 * i]);
}

// V fp16 head layout [bh][s][dh] -> Vt fp16 [bh][dh][s]
__global__ __launch_bounds__(256) void transpose_v_h(
    const __half* __restrict__ V, __half* __restrict__ Vt)
{
    __shared__ __half t[32][34];
    const int bh = blockIdx.z;
    const int s0 = blockIdx.x * 32, d0 = blockIdx.y * 32;
    const __half* Vb = V + (size_t)bh * Sv * DHv;
    __half* Ob = Vt + (size_t)bh * DHv * Sv;
    const int tx = threadIdx.x & 31, ty = threadIdx.x >> 5;
#pragma unroll
    for (int i = 0; i < 4; ++i)
        t[ty + 8 * i][tx] = Vb[(size_t)(s0 + ty + 8 * i) * DHv + d0 + tx];
    __syncthreads();
#pragma unroll
    for (int i = 0; i < 4; ++i)
        Ob[(size_t)(d0 + ty + 8 * i) * Sv + s0 + tx] = t[tx][ty + 8 * i];
}

// ===== fp16 GEMM mainloop (BK=32), 128x128 tile, 64x32 warp tiles ============
__device__ __forceinline__ void f16_gemm_main(
    const __half* __restrict__ A, const __half* __restrict__ Bt,
    int m0, int n0, float c[4][4][4],
    __half (*As)[40], __half (*Bs)[40])
{
    const int tid = threadIdx.x, lane = tid & 31, warp = tid >> 5;
    const int wm = (warp >> 2) * 64, wn = (warp & 3) * 32;
    const int g = lane >> 2, qd = lane & 3;

    for (int k0 = 0; k0 < Dv; k0 += 32) {
#pragma unroll
        for (int it = 0; it < 2; ++it) {
            int idx = tid + it * 256;
            int row = idx >> 2, c8 = (idx & 3) * 8;
            *reinterpret_cast<uint4*>(&As[row][c8]) =
                *reinterpret_cast<const uint4*>(A + (size_t)(m0 + row) * Dv + k0 + c8);
            *reinterpret_cast<uint4*>(&Bs[row][c8]) =
                *reinterpret_cast<const uint4*>(Bt + (size_t)(n0 + row) * Dv + k0 + c8);
        }
        __syncthreads();
#pragma unroll
        for (int kk = 0; kk < 32; kk += 16) {
            unsigned af[4][4], bf[4][2];
#pragma unroll
            for (int mt = 0; mt < 4; ++mt) {
                int r = wm + mt * 16 + g;
                af[mt][0] = *reinterpret_cast<const unsigned*>(&As[r][kk + 2 * qd]);
                af[mt][1] = *reinterpret_cast<const unsigned*>(&As[r + 8][kk + 2 * qd]);
                af[mt][2] = *reinterpret_cast<const unsigned*>(&As[r][kk + 2 * qd + 8]);
                af[mt][3] = *reinterpret_cast<const unsigned*>(&As[r + 8][kk + 2 * qd + 8]);
            }
#pragma unroll
            for (int nt = 0; nt < 4; ++nt) {
                int cn = wn + nt * 8 + g;
                bf[nt][0] = *reinterpret_cast<const unsigned*>(&Bs[cn][kk + 2 * qd]);
                bf[nt][1] = *reinterpret_cast<const unsigned*>(&Bs[cn][kk + 2 * qd + 8]);
            }
#pragma unroll
            for (int mt = 0; mt < 4; ++mt)
#pragma unroll
                for (int nt = 0; nt < 4; ++nt) mma_f16(c[mt][nt], af[mt], bf[nt]);
        }
        __syncthreads();
    }
}

// ============ QKV projection: fp16 MMA, epilogue fp16 head layout ============
__global__ __launch_bounds__(256, 2) void gemm_qkv(
    const __half* __restrict__ A, const __half* __restrict__ Wt,
    const float* __restrict__ bq, const float* __restrict__ bk, const float* __restrict__ bvb,
    __half* __restrict__ qh, __half* __restrict__ kh, __half* __restrict__ vh)
{
    __shared__ __half As[128][40];
    __shared__ __half Bs[128][40];
    const __half* Bt = Wt + (size_t)blockIdx.z * Dv * Dv;
    const float* bias = (blockIdx.z == 0) ? bq : (blockIdx.z == 1) ? bk : bvb;
    __half* out = (blockIdx.z == 0) ? qh : (blockIdx.z == 1) ? kh : vh;
    const int m0 = blockIdx.y * 128, n0 = blockIdx.x * 128;
    const int lane = threadIdx.x & 31, warp = threadIdx.x >> 5;
    const int wm = (warp >> 2) * 64, wn = (warp & 3) * 32;
    const int g = lane >> 2, qd = lane & 3;

    float c[4][4][4];
#pragma unroll
    for (int mt = 0; mt < 4; ++mt)
#pragma unroll
        for (int nt = 0; nt < 4; ++nt)
#pragma unroll
            for (int i = 0; i < 4; ++i) c[mt][nt][i] = 0.f;

    f16_gemm_main(A, Bt, m0, n0, c, As, Bs);

#pragma unroll
    for (int mt = 0; mt < 4; ++mt) {
#pragma unroll
        for (int i = 0; i < 2; ++i) {
            int row = m0 + wm + mt * 16 + g + 8 * i;
            int b = row >> 10, s = row & 1023;
#pragma unroll
            for (int nt = 0; nt < 4; ++nt) {
                int col = n0 + wn + nt * 8 + 2 * qd;
                float2 bb = *reinterpret_cast<const float2*>(bias + col);
                int h = col >> 6, d = col & 63;
                *reinterpret_cast<__half2*>(out + ((size_t)(b * Hv + h) * Sv + s) * DHv + d) =
                    __floats2half2_rn(c[mt][nt][2 * i + 0] + bb.x,
                                      c[mt][nt][2 * i + 1] + bb.y);
            }
        }
    }
}

// ============ out-projection: fp16 MMA, fp32 bias+resid -> fp32 out ==========
__global__ __launch_bounds__(256, 2) void gemm_out(
    const __half* __restrict__ A, const __half* __restrict__ Bt,
    const float* __restrict__ bias, const float* __restrict__ resid,
    float* __restrict__ out)
{
    __shared__ __half As[128][40];
    __shared__ __half Bs[128][40];
    const int m0 = blockIdx.y * 128, n0 = blockIdx.x * 128;
    const int lane = threadIdx.x & 31, warp = threadIdx.x >> 5;
    const int wm = (warp >> 2) * 64, wn = (warp & 3) * 32;
    const int g = lane >> 2, qd = lane & 3;

    float c[4][4][4];
#pragma unroll
    for (int mt = 0; mt < 4; ++mt)
#pragma unroll
        for (int nt = 0; nt < 4; ++nt)
#pragma unroll
            for (int i = 0; i < 4; ++i) c[mt][nt][i] = 0.f;

    f16_gemm_main(A, Bt, m0, n0, c, As, Bs);

#pragma unroll
    for (int mt = 0; mt < 4; ++mt) {
#pragma unroll
        for (int i = 0; i < 2; ++i) {
            int row = m0 + wm + mt * 16 + g + 8 * i;
#pragma unroll
            for (int nt = 0; nt < 4; ++nt) {
                int col = n0 + wn + nt * 8 + 2 * qd;
                float2 bb = *reinterpret_cast<const float2*>(bias + col);
                float2 rv = *reinterpret_cast<const float2*>(resid + (size_t)row * Dv + col);
                float2 v;
                v.x = c[mt][nt][2 * i + 0] + bb.x + rv.x;
                v.y = c[mt][nt][2 * i + 1] + bb.y + rv.y;
                *reinterpret_cast<float2*>(out + (size_t)row * Dv + col) = v;
            }
        }
    }
}

// ====== qk fp16 MMA (whole-tile staging) + exp epilogue ======================
__global__ __launch_bounds__(256, 2) void qk_exp(
    const __half* __restrict__ Q, const __half* __restrict__ Km,
    const float* __restrict__ mask, __half* __restrict__ att,
    float* __restrict__ psum)
{
    __shared__ __half As[128][72];
    __shared__ __half Bs[128][72];
    __shared__ float sm_mask[128];
    __shared__ float sm_rs[128][4];
    const int tid = threadIdx.x, lane = tid & 31, warp = tid >> 5;
    const int wm = (warp >> 2) * 64, wn = (warp & 3) * 32;
    const int g = lane >> 2, qd = lane & 3;
    const int n0 = blockIdx.x * 128, m0 = blockIdx.y * 128;
    const int bh = blockIdx.z, bb = bh / Hv;
    const size_t base = (size_t)bh * Sv * DHv;

    if (tid < 128) sm_mask[tid] = mask[(size_t)bb * Sv + n0 + tid];

#pragma unroll
    for (int it = 0; it < 4; ++it) {
        int idx = tid + it * 256;
        int row = idx >> 3, c8 = (idx & 7) * 8;
        *reinterpret_cast<uint4*>(&As[row][c8]) =
            *reinterpret_cast<const uint4*>(Q + base + (size_t)(m0 + row) * DHv + c8);
        *reinterpret_cast<uint4*>(&Bs[row][c8]) =
            *reinterpret_cast<const uint4*>(Km + base + (size_t)(n0 + row) * DHv + c8);
    }
    __syncthreads();

    float c[4][4][4];
#pragma unroll
    for (int mt = 0; mt < 4; ++mt)
#pragma unroll
        for (int nt = 0; nt < 4; ++nt)
#pragma unroll
            for (int i = 0; i < 4; ++i) c[mt][nt][i] = 0.f;

#pragma unroll
    for (int kk = 0; kk < 64; kk += 16) {
        unsigned af[4][4], bf[4][2];
#pragma unroll
        for (int mt = 0; mt < 4; ++mt) {
            int r = wm + mt * 16 + g;
            af[mt][0] = *reinterpret_cast<const unsigned*>(&As[r][kk + 2 * qd]);
            af[mt][1] = *reinterpret_cast<const unsigned*>(&As[r + 8][kk + 2 * qd]);
            af[mt][2] = *reinterpret_cast<const unsigned*>(&As[r][kk + 2 * qd + 8]);
            af[mt][3] = *reinterpret_cast<const unsigned*>(&As[r + 8][kk + 2 * qd + 8]);
        }
#pragma unroll
        for (int nt = 0; nt < 4; ++nt) {
            int cn = wn + nt * 8 + g;
            bf[nt][0] = *reinterpret_cast<const unsigned*>(&Bs[cn][kk + 2 * qd]);
            bf[nt][1] = *reinterpret_cast<const unsigned*>(&Bs[cn][kk + 2 * qd + 8]);
        }
#pragma unroll
        for (int mt = 0; mt < 4; ++mt)
#pragma unroll
            for (int nt = 0; nt < 4; ++nt) mma_f16(c[mt][nt], af[mt], bf[nt]);
    }

    const size_t ab = (size_t)bh * Sv * Sv;
    float rsum[4][2];
#pragma unroll
    for (int mt = 0; mt < 4; ++mt) {
#pragma unroll
        for (int i = 0; i < 2; ++i) {
            rsum[mt][i] = 0.f;
            int row = m0 + wm + mt * 16 + g + 8 * i;
#pragma unroll
            for (int nt = 0; nt < 4; ++nt) {
                int lcol = wn + nt * 8 + 2 * qd;
                float e0 = fexp(fmaf(c[mt][nt][2 * i + 0], 0.125f, sm_mask[lcol]));
                float e1 = fexp(fmaf(c[mt][nt][2 * i + 1], 0.125f, sm_mask[lcol + 1]));
                rsum[mt][i] += e0 + e1;
                *reinterpret_cast<__half2*>(att + ab + (size_t)row * Sv + n0 + lcol) =
                    __floats2half2_rn(e0, e1);
            }
        }
    }
#pragma unroll
    for (int mt = 0; mt < 4; ++mt)
#pragma unroll
        for (int i = 0; i < 2; ++i) {
            float r = rsum[mt][i];
            r += __shfl_xor_sync(0xffffffffu, r, 1);
            r += __shfl_xor_sync(0xffffffffu, r, 2);
            if ((lane & 3) == 0) sm_rs[wm + mt * 16 + g + 8 * i][warp & 3] = r;
        }
    __syncthreads();
    if (tid < 128) {
        float s = (sm_rs[tid][0] + sm_rs[tid][1]) + (sm_rs[tid][2] + sm_rs[tid][3]);
        psum[((size_t)bh * Sv + m0 + tid) * 8 + blockIdx.x] = s;
    }
}

// ---------------- combine partials -> inv_sum1 --------------------------------
__global__ __launch_bounds__(256) void stats_combine(
    const float* __restrict__ psum, float* __restrict__ inv1)
{
    int i = blockIdx.x * 256 + threadIdx.x;
    const float* p = psum + (size_t)i * 8;
    float s = ((p[0] + p[1]) + (p[2] + p[3])) + ((p[4] + p[5]) + (p[6] + p[7]));
    inv1[i] = 1.f / s;
}

// ---- mix (round-8 proven structure): pv/pr loaded once, per-head blockReduce
__global__ __launch_bounds__(256) void mix2(
    __half* __restrict__ att, const float* __restrict__ prev,
    const float* __restrict__ inv1g, const float* __restrict__ cw_g,
    const float* __restrict__ cb_g)
{
    __shared__ float cw[144];
    __shared__ float cb[12];
    __shared__ float red[9];
    const int t = threadIdx.x;
    const int qi = blockIdx.x;
    const int b = blockIdx.y;
    if (t < 144) cw[t] = cw_g[t];
    if (t < 12) cb[t] = cb_g[t];
    __syncthreads();

    float pv[12][4];
#pragma unroll
    for (int i = 0; i < 12; ++i) {
        const __half2* pa = reinterpret_cast<const __half2*>(
            att + ((size_t)(b * Hv + i) * Sv + qi) * Sv + 4 * t);
        __half2 h0 = pa[0], h1 = pa[1];
        float inv = inv1g[(size_t)(b * Hv + i) * Sv + qi];
        pv[i][0] = __low2float(h0) * inv;  pv[i][1] = __high2float(h0) * inv;
        pv[i][2] = __low2float(h1) * inv;  pv[i][3] = __high2float(h1) * inv;
    }
    float pr[12][4];
#pragma unroll
    for (int i = 0; i < 12; ++i) {
        float4 p4 = *reinterpret_cast<const float4*>(
            prev + ((size_t)(b * Hv + i) * Sv + qi) * Sv + 4 * t);
        pr[i][0] = p4.x; pr[i][1] = p4.y; pr[i][2] = p4.z; pr[i][3] = p4.w;
    }

#pragma unroll
    for (int o = 0; o < 12; ++o) {
        float e2[4], ls = 0.f;
#pragma unroll
        for (int j = 0; j < 4; ++j) {
            float a = cb[o];
#pragma unroll
            for (int i = 0; i < 12; ++i) a = fmaf(cw[o * 12 + i], pr[i][j], a);
            float mixd = fmaf(0.5f, a, 0.5f * pv[o][j]);
            e2[j] = fexp(mixd);
            ls += e2[j];
        }
        float sum2 = blockReduce256(ls, red);
        float inv2 = 1.f / sum2;
        __half2* oa = reinterpret_cast<__half2*>(
            att + ((size_t)(b * Hv + o) * Sv + qi) * Sv + 4 * t);
        oa[0] = __floats2half2_rn(e2[0] * inv2, e2[1] * inv2);
        oa[1] = __floats2half2_rn(e2[2] * inv2, e2[3] * inv2);
    }
}

// ============ ctx = probs @ V, fp16 MMA, 128x64 tile; ctx stored fp16 ========
__global__ __launch_bounds__(256, 2) void av_f16(
    const __half* __restrict__ P, const __half* __restrict__ Vt, __half* __restrict__ ctx)
{
    __shared__ __half As[128][40];
    __shared__ __half Bs[64][40];
    const int tid = threadIdx.x, lane = tid & 31, warp = tid >> 5;
    const int wm = (warp >> 2) * 64, wn = (warp & 3) * 16;
    const int g = lane >> 2, qd = lane & 3;
    const int q0 = blockIdx.x * 128;
    const int bh = blockIdx.y;
    const int b = bh / Hv, h = bh % Hv;
    const __half* A = P + (size_t)bh * Sv * Sv;
    const __half* Vb = Vt + (size_t)bh * DHv * Sv;

    float c[4][2][4];
#pragma unroll
    for (int mt = 0; mt < 4; ++mt)
#pragma unroll
        for (int nt = 0; nt < 2; ++nt)
#pragma unroll
            for (int i = 0; i < 4; ++i) c[mt][nt][i] = 0.f;

    for (int k0 = 0; k0 < Sv; k0 += 32) {
#pragma unroll
        for (int it = 0; it < 2; ++it) {
            int idx = tid + it * 256;
            int row = idx >> 2, c8 = (idx & 3) * 8;
            uint4 v = *reinterpret_cast<const uint4*>(A + (size_t)(q0 + row) * Sv + k0 + c8);
            *reinterpret_cast<uint4*>(&As[row][c8]) = v;
        }
        {
            int row = tid >> 2, c8 = (tid & 3) * 8;
            uint4 v = *reinterpret_cast<const uint4*>(Vb + (size_t)row * Sv + k0 + c8);
            *reinterpret_cast<uint4*>(&Bs[row][c8]) = v;
        }
        __syncthreads();
#pragma unroll
        for (int kk = 0; kk < 32; kk += 16) {
            unsigned af[4][4], bf[2][2];
#pragma unroll
            for (int mt = 0; mt < 4; ++mt) {
                int r = wm + mt * 16 + g;
                af[mt][0] = *reinterpret_cast<const unsigned*>(&As[r][kk + 2 * qd]);
                af[mt][1] = *reinterpret_cast<const unsigned*>(&As[r + 8][kk + 2 * qd]);
                af[mt][2] = *reinterpret_cast<const unsigned*>(&As[r][kk + 2 * qd + 8]);
                af[mt][3] = *reinterpret_cast<const unsigned*>(&As[r + 8][kk + 2 * qd + 8]);
            }
#pragma unroll
            for (int nt = 0; nt < 2; ++nt) {
                int cn = wn + nt * 8 + g;
                bf[nt][0] = *reinterpret_cast<const unsigned*>(&Bs[cn][kk + 2 * qd]);
                bf[nt][1] = *reinterpret_cast<const unsigned*>(&Bs[cn][kk + 2 * qd + 8]);
            }
#pragma unroll
            for (int mt = 0; mt < 4; ++mt)
#pragma unroll
                for (int nt = 0; nt < 2; ++nt) mma_f16(c[mt][nt], af[mt], bf[nt]);
        }
        __syncthreads();
    }

#pragma unroll
    for (int mt = 0; mt < 4; ++mt) {
#pragma unroll
        for (int i = 0; i < 2; ++i) {
            int row = q0 + wm + mt * 16 + g + 8 * i;
#pragma unroll
            for (int nt = 0; nt < 2; ++nt) {
                int col = wn + nt * 8 + 2 * qd;
                *reinterpret_cast<__half2*>(ctx + ((size_t)b * Sv + row) * Dv + h * DHv + col) =
                    __floats2half2_rn(c[mt][nt][2 * i + 0], c[mt][nt][2 * i + 1]);
            }
        }
    }
}

// ---------------- LayerNorm over last dim (768) -------------------------------
__global__ __launch_bounds__(256) void layernorm_row(
    const float* __restrict__ pre, const float* __restrict__ w,
    const float* __restrict__ bb, float* __restrict__ out)
{
    __shared__ float red[9];
    const int t = threadIdx.x;
    const size_t row = blockIdx.x;
    const float* x = pre + row * Dv;

    float v[3];
#pragma unroll
    for (int j = 0; j < 3; ++j) v[j] = x[t + 256 * j];
    float s = v[0] + v[1] + v[2];
    s = blockReduce256(s, red);
    float u = s * (1.f / 768.f);
    float d0 = v[0] - u, d1 = v[1] - u, d2 = v[2] - u;
    float sq = d0 * d0 + d1 * d1 + d2 * d2;
    sq = blockReduce256(sq, red);
    float var = sq * (1.f / 768.f);
    float rr = rsqrtf(var + 1e-12f);
    float dd[3] = {d0, d1, d2};
#pragma unroll
    for (int j = 0; j < 3; ++j) {
        int ci = t + 256 * j;
        out[row * Dv + ci] = dd[j] * rr * w[ci] + bb[ci];
    }
}

// ------------------------------------------------------------------------------
extern "C" void kernel_launch(void* const* d_in, const int* in_sizes, int n_in,
                              void* d_out, int out_size)
{
    const float* hidden = (const float*)d_in[0];
    const float* mask   = (const float*)d_in[1];
    const float* prev   = (const float*)d_in[2];
    const float* Wq = (const float*)d_in[3];
    const float* bq = (const float*)d_in[4];
    const float* Wk = (const float*)d_in[5];
    const float* bk = (const float*)d_in[6];
    const float* Wv = (const float*)d_in[7];
    const float* bvp = (const float*)d_in[8];
    const float* cw = (const float*)d_in[9];
    const float* cb = (const float*)d_in[10];
    const float* Wo = (const float*)d_in[11];
    const float* bo = (const float*)d_in[12];
    const float* lnw = (const float*)d_in[13];
    const float* lnb = (const float*)d_in[14];
    float* out = (float*)d_out;

    float *pre, *psum, *inv1;
    __half *att, *wth, *vt, *qh, *kh, *vh, *hh, *ctx;
    cudaGetSymbolAddress((void**)&pre,  g_pre);
    cudaGetSymbolAddress((void**)&ctx,  g_ctx);
    cudaGetSymbolAddress((void**)&att,  g_att);
    cudaGetSymbolAddress((void**)&wth,  g_wth);
    cudaGetSymbolAddress((void**)&vt,   g_vt);
    cudaGetSymbolAddress((void**)&qh,   g_qh);
    cudaGetSymbolAddress((void**)&kh,   g_kh);
    cudaGetSymbolAddress((void**)&vh,   g_vh);
    cudaGetSymbolAddress((void**)&hh,   g_hh);
    cudaGetSymbolAddress((void**)&psum, g_psum);
    cudaGetSymbolAddress((void**)&inv1, g_inv1);

    hidden_to_h<<<(Mv * Dv) / (256 * 8), 256>>>(hidden, hh);
    transpose_w4<<<dim3(24, 24, 4), 256>>>(Wq, Wk, Wv, Wo, wth);

    gemm_qkv<<<dim3(Dv / 128, Mv / 128, 3), 256>>>(hh, wth, bq, bk, bvp, qh, kh, vh);

    transpose_v_h<<<dim3(Sv / 32, DHv / 32, BHv), 256>>>(vh, vt);

    qk_exp<<<dim3(Sv / 128, Sv / 128, BHv), 256>>>(qh, kh, mask, att, psum);

    stats_combine<<<(BHv * Sv) / 256, 256>>>(psum, inv1);

    mix2<<<dim3(Sv, Bv), 256>>>(att, prev, inv1, cw, cb);

    av_f16<<<dim3(Sv / 128, BHv), 256>>>(att, vt, ctx);

    gemm_out<<<dim3(Dv / 128, Mv / 128), 256>>>(ctx, wth + (size_t)3 * Dv * Dv, bo, hidden, pre);

    layernorm_row<<<Mv, 256>>>(pre, lnw, lnb, out);
}